// round 12
// baseline (speedup 1.0000x reference)
#include <cuda_runtime.h>
#include <cuda_bf16.h>
#include <cstdint>
#include <math.h>

// Problem constants
#define M_DIM 16384          // B*S
#define K_DIM 4864           // IN_DIM
#define N_DIM 640            // G*V
#define NVARS 320
#define NGROUPS 2
#define CVD   128
#define MARGIN 0.02f

// GEMM tiling: CTA 128x64, 4 warps (2Mx2N), warp tile 64x32, 3 CTAs/SM
#define BM 128
#define BN 64
#define BK 64
#define STAGES 3
#define NKT (K_DIM / BK)                 // 76
#define NTILES (N_DIM / BN)              // 10
#define NSLOT 4

#define SM_A_STAGE (BM * BK * 2)         // 16 KB
#define SM_B_STAGE (BN * BK * 2)         // 8 KB
#define SM_STAGE   (SM_A_STAGE + SM_B_STAGE)  // 24 KB
#define SM_TOTAL   (STAGES * SM_STAGE)   // 72 KB -> 3 CTAs/SM

// ---------------- scratch ----------------
__device__ __nv_bfloat16 g_Abf[(size_t)M_DIM * K_DIM];   // ~159 MB
__device__ __nv_bfloat16 g_Btbf[(size_t)N_DIM * K_DIM];  // ~6.2 MB  W^T bf16 [n][k]
__device__ float         g_Wt[(size_t)N_DIM * K_DIM];    // ~12.5 MB W^T fp32 [n][k]
__device__ float g_candv[(size_t)M_DIM * NTILES * NSLOT]; // 2.6 MB candidate values
__device__ int   g_candc[(size_t)M_DIM * NTILES * NSLOT]; // 2.6 MB candidate cols (global)
__device__ int   g_counts[N_DIM];

// ---------------- stream/event plumbing (created pre-main; no device allocs) ----------------
struct OverlapCtx {
    cudaStream_t s1 = nullptr;
    cudaEvent_t  eFork = nullptr, eJoin = nullptr;
    bool ok = false;
    OverlapCtx() {
        if (cudaStreamCreateWithFlags(&s1, cudaStreamNonBlocking) == cudaSuccess &&
            cudaEventCreateWithFlags(&eFork, cudaEventDisableTiming) == cudaSuccess &&
            cudaEventCreateWithFlags(&eJoin, cudaEventDisableTiming) == cudaSuccess)
            ok = true;
    }
};
static OverlapCtx g_ovl;

// ---------------- helpers ----------------
__device__ __forceinline__ uint32_t smem_u32(const void* p) {
    uint32_t a;
    asm("{ .reg .u64 t; cvta.to.shared.u64 t, %1; cvt.u32.u64 %0, t; }" : "=r"(a) : "l"(p));
    return a;
}
__device__ __forceinline__ void ldsm_x4(uint32_t* r, uint32_t addr) {
    asm volatile("ldmatrix.sync.aligned.m8n8.x4.shared.b16 {%0,%1,%2,%3}, [%4];"
        : "=r"(r[0]), "=r"(r[1]), "=r"(r[2]), "=r"(r[3]) : "r"(addr));
}

// ---------------- kernel 1: convert hidden_states fp32 -> bf16 (range) ----------------
__global__ void conv_a_kernel(const float* __restrict__ A, int base) {
    int i = base + blockIdx.x * blockDim.x + threadIdx.x;
    float4 v = reinterpret_cast<const float4*>(A)[i];
    __nv_bfloat162* o = reinterpret_cast<__nv_bfloat162*>(g_Abf) + (size_t)i * 2;
    o[0] = __floats2bfloat162_rn(v.x, v.y);
    o[1] = __floats2bfloat162_rn(v.z, v.w);
}

// ---------------- kernel 2: transpose W + zero counts ----------------
__global__ void trans_w_kernel(const float* __restrict__ W) {
    __shared__ float tile[32][33];
    const int tx = threadIdx.x & 31;
    const int ty = threadIdx.x >> 5;
    if (blockIdx.x == 0 && blockIdx.y == 0) {
        for (int i = threadIdx.x; i < N_DIM; i += 256) g_counts[i] = 0;
    }
    int x = blockIdx.x * 32 + tx;
    int y0 = blockIdx.y * 32;
    #pragma unroll
    for (int j = ty; j < 32; j += 8)
        tile[j][tx] = W[(size_t)(y0 + j) * N_DIM + x];
    __syncthreads();
    #pragma unroll
    for (int j = ty; j < 32; j += 8) {
        int n = blockIdx.x * 32 + j;
        int k = y0 + tx;
        float val = tile[tx][j];
        g_Wt[(size_t)n * K_DIM + k] = val;
        g_Btbf[(size_t)n * K_DIM + k] = __float2bfloat16_rn(val);
    }
}

// ---------------- kernel 3: bf16 HMMA GEMM + threshold candidate epilogue ----------------
// CTA 128x64, BK=64, 3-stage cp.async, ldmatrix fragments, 4 warps (2Mx2N),
// warp tile 64x32, 3 CTAs/SM, one barrier per K-step. m_base selects the M half.
__global__ __launch_bounds__(128, 3) void gemm_kernel(const float* __restrict__ bias, int m_base) {
    extern __shared__ char smem[];
    const uint32_t su = smem_u32(smem);
    const int tid  = threadIdx.x;
    const int lane = tid & 31;
    const int warp = tid >> 5;       // 0..3
    const int wm = warp >> 1;        // 0..1  (M)
    const int wn = warp & 1;         // 0..1  (N)
    const int cta_m = m_base + blockIdx.y * BM;
    const int cta_n = blockIdx.x * BN;

    float acc[4][4][4];              // [mt][nt][frag]
    #pragma unroll
    for (int a = 0; a < 4; a++)
        #pragma unroll
        for (int b = 0; b < 4; b++)
            #pragma unroll
            for (int c = 0; c < 4; c++) acc[a][b][c] = 0.0f;

    // ---- fragment smem offsets (128B rows; swizzle: chunk ^= row&7) ----
    const int sw = lane & 7;
    uint32_t aOff[4];
    #pragma unroll
    for (int mt = 0; mt < 4; mt++)
        aOff[mt] = (uint32_t)((wm * 64 + mt * 16 + (lane & 15)) * 128);
    const int aChunkHi = lane >> 4;
    uint32_t bOff[2];
    #pragma unroll
    for (int p = 0; p < 2; p++)
        bOff[p] = (uint32_t)((wn * 32 + p * 16 + ((lane >> 4) << 3) + (lane & 7)) * 128);
    const int bChunkHi = (lane >> 3) & 1;

    // ---- stage loader: 16B cp.async, swizzled, 128 threads ----
    const __nv_bfloat16* Ag = g_Abf + (size_t)cta_m * K_DIM;
    const __nv_bfloat16* Bg = g_Btbf + (size_t)cta_n * K_DIM;
    auto load_stage = [&](int kt) {
        const int st = kt % STAGES;
        const int k0 = kt * BK;
        const uint32_t aB = su + st * SM_STAGE;
        const uint32_t bB = aB + SM_A_STAGE;
        #pragma unroll
        for (int i = 0; i < 8; i++) {          // A: 1024 chunks / 128 thr
            int ch = tid + 128 * i;
            int row = ch >> 3, c = ch & 7;
            uint32_t dst = aB + row * 128 + ((c ^ (row & 7)) << 4);
            const void* src = Ag + (size_t)row * K_DIM + k0 + c * 8;
            asm volatile("cp.async.cg.shared.global [%0], [%1], 16;" :: "r"(dst), "l"(src));
        }
        #pragma unroll
        for (int i = 0; i < 4; i++) {          // B: 512 chunks / 128 thr
            int ch = tid + 128 * i;
            int row = ch >> 3, c = ch & 7;
            uint32_t dst = bB + row * 128 + ((c ^ (row & 7)) << 4);
            const void* src = Bg + (size_t)row * K_DIM + k0 + c * 8;
            asm volatile("cp.async.cg.shared.global [%0], [%1], 16;" :: "r"(dst), "l"(src));
        }
    };

    load_stage(0); asm volatile("cp.async.commit_group;");
    load_stage(1); asm volatile("cp.async.commit_group;");

    for (int kt = 0; kt < NKT; kt++) {
        if (kt + 1 < NKT) asm volatile("cp.async.wait_group 1;");
        else              asm volatile("cp.async.wait_group 0;");
        __syncthreads();   // orders stage-kt visibility AND protects stage (kt+2)%3 reuse

        if (kt + 2 < NKT) { load_stage(kt + 2); asm volatile("cp.async.commit_group;"); }

        const uint32_t stBase = su + (kt % STAGES) * SM_STAGE;
        const uint32_t bBase  = stBase + SM_A_STAGE;

        #pragma unroll
        for (int kk = 0; kk < 4; kk++) {
            uint32_t afr[4][4];
            #pragma unroll
            for (int mt = 0; mt < 4; mt++) {
                uint32_t addr = stBase + aOff[mt] + (((kk * 2 + aChunkHi) ^ sw) << 4);
                ldsm_x4(afr[mt], addr);
            }
            uint32_t bfr[2][4];
            #pragma unroll
            for (int p = 0; p < 2; p++) {
                uint32_t addr = bBase + bOff[p] + (((kk * 2 + bChunkHi) ^ sw) << 4);
                ldsm_x4(bfr[p], addr);
            }
            #pragma unroll
            for (int mt = 0; mt < 4; mt++) {
                #pragma unroll
                for (int p = 0; p < 2; p++) {
                    asm volatile(
                        "mma.sync.aligned.m16n8k16.row.col.f32.bf16.bf16.f32 "
                        "{%0,%1,%2,%3}, {%4,%5,%6,%7}, {%8,%9}, {%0,%1,%2,%3};\n"
                        : "+f"(acc[mt][2*p][0]), "+f"(acc[mt][2*p][1]),
                          "+f"(acc[mt][2*p][2]), "+f"(acc[mt][2*p][3])
                        : "r"(afr[mt][0]), "r"(afr[mt][1]), "r"(afr[mt][2]), "r"(afr[mt][3]),
                          "r"(bfr[p][0]), "r"(bfr[p][1]));
                    asm volatile(
                        "mma.sync.aligned.m16n8k16.row.col.f32.bf16.bf16.f32 "
                        "{%0,%1,%2,%3}, {%4,%5,%6,%7}, {%8,%9}, {%0,%1,%2,%3};\n"
                        : "+f"(acc[mt][2*p+1][0]), "+f"(acc[mt][2*p+1][1]),
                          "+f"(acc[mt][2*p+1][2]), "+f"(acc[mt][2*p+1][3])
                        : "r"(afr[mt][0]), "r"(afr[mt][1]), "r"(afr[mt][2]), "r"(afr[mt][3]),
                          "r"(bfr[p][2]), "r"(bfr[p][3]));
                }
            }
        }
    }

    // ---- epilogue: bias + exact threshold candidate extraction ----
    __syncthreads();                      // all LDSM done -> reuse stage smem
    float* sh_max = reinterpret_cast<float*>(smem);              // [128][8]
    float* sh_thr = reinterpret_cast<float*>(smem + 4096);       // [128]
    int*   sh_cnt = reinterpret_cast<int*>(smem + 4608);         // [128]
    float* sh_cv  = reinterpret_cast<float*>(smem + 5120);       // [128][4]
    int*   sh_cc  = reinterpret_cast<int*>(smem + 7168);         // [128][4]

    const int g = lane >> 2;
    const int t = lane & 3;
    // add bias in place
    #pragma unroll
    for (int nt = 0; nt < 4; nt++) {
        float2 bv = *reinterpret_cast<const float2*>(bias + cta_n + wn * 32 + nt * 8 + 2 * t);
        #pragma unroll
        for (int mt = 0; mt < 4; mt++) {
            acc[mt][nt][0] += bv.x; acc[mt][nt][1] += bv.y;
            acc[mt][nt][2] += bv.x; acc[mt][nt][3] += bv.y;
        }
    }
    const int slot = wn * 4 + t;
    // phase A: per-thread row-half max
    #pragma unroll
    for (int mt = 0; mt < 4; mt++) {
        #pragma unroll
        for (int half = 0; half < 2; half++) {
            int rowL = wm * 64 + mt * 16 + g + half * 8;
            float m = -1e30f;
            #pragma unroll
            for (int nt = 0; nt < 4; nt++) {
                m = fmaxf(m, acc[mt][nt][half * 2 + 0]);
                m = fmaxf(m, acc[mt][nt][half * 2 + 1]);
            }
            sh_max[rowL * 8 + slot] = m;
        }
    }
    __syncthreads();
    // phase B: row threshold + init
    if (tid < 128) {
        float m = -1e30f;
        #pragma unroll
        for (int s = 0; s < 8; s++) m = fmaxf(m, sh_max[tid * 8 + s]);
        sh_thr[tid] = m - MARGIN;
        sh_cnt[tid] = 0;
        #pragma unroll
        for (int j = 0; j < NSLOT; j++) { sh_cv[tid * NSLOT + j] = -1e30f; sh_cc[tid * NSLOT + j] = 0; }
    }
    __syncthreads();
    // phase C: scan & push candidates
    #pragma unroll
    for (int mt = 0; mt < 4; mt++) {
        #pragma unroll
        for (int half = 0; half < 2; half++) {
            int rowL = wm * 64 + mt * 16 + g + half * 8;
            float thr = sh_thr[rowL];
            #pragma unroll
            for (int nt = 0; nt < 4; nt++) {
                #pragma unroll
                for (int e = 0; e < 2; e++) {
                    float v = acc[mt][nt][half * 2 + e];
                    if (v >= thr) {
                        int s = atomicAdd(&sh_cnt[rowL], 1);
                        if (s < NSLOT) {
                            sh_cv[rowL * NSLOT + s] = v;
                            sh_cc[rowL * NSLOT + s] = cta_n + wn * 32 + nt * 8 + 2 * t + e;
                        }
                    }
                }
            }
        }
    }
    __syncthreads();
    // phase D: write 4-slot record
    if (tid < 128) {
        size_t gb = ((size_t)(cta_m + tid) * NTILES + blockIdx.x) * NSLOT;
        *reinterpret_cast<float4*>(&g_candv[gb]) = *reinterpret_cast<float4*>(&sh_cv[tid * NSLOT]);
        *reinterpret_cast<int4*>(&g_candc[gb])   = *reinterpret_cast<int4*>(&sh_cc[tid * NSLOT]);
    }
}

// ---------------- kernel 4: finalize = group merge, margin rescue, histogram, gather ----------------
// one warp per (row, group); 8 warps per block
__global__ __launch_bounds__(256) void finalize_kernel(const float* __restrict__ hidden,
                                                       const float* __restrict__ bias,
                                                       const float* __restrict__ cv,
                                                       float* __restrict__ out) {
    const int lane = threadIdx.x & 31;
    const int gw = blockIdx.x * 8 + (threadIdx.x >> 5);  // 0..32767
    const int r = gw >> 1;
    const int g = gw & 1;

    // lanes 0..19 hold the 5 tiles x 4 slots for this group
    float v = -1e30f;
    int   c = 0x7fffffff;
    if (lane < 5 * NSLOT) {
        size_t base = ((size_t)r * NTILES + g * 5 + (lane >> 2)) * NSLOT + (lane & 3);
        v = g_candv[base];
        c = g_candc[base];
    }
    float mx = v;
    #pragma unroll
    for (int off = 16; off > 0; off >>= 1)
        mx = fmaxf(mx, __shfl_xor_sync(0xffffffffu, mx, off));

    unsigned mask = __ballot_sync(0xffffffffu, v >= mx - MARGIN);
    int winner;
    if (__popc(mask) == 1) {
        winner = __shfl_sync(0xffffffffu, c, __ffs(mask) - 1);
    } else {
        // exact fp32 rescore of all candidates; lowest col wins ties
        const float* hrow = hidden + (size_t)r * K_DIM;
        float bb = -INFINITY;
        int bi = 0x7fffffff;
        unsigned m = mask;
        while (m) {
            int src = __ffs(m) - 1;
            m &= m - 1;
            int col = __shfl_sync(0xffffffffu, c, src);   // global col 0..639
            const float* wrow = g_Wt + (size_t)col * K_DIM;
            float s = 0.0f;
            for (int k = lane; k < K_DIM; k += 32)
                s = fmaf(hrow[k], wrow[k], s);
            #pragma unroll
            for (int off = 16; off > 0; off >>= 1)
                s += __shfl_xor_sync(0xffffffffu, s, off);
            s += bias[col];
            if (s > bb || (s == bb && col < bi)) { bb = s; bi = col; }
        }
        winner = bi;
    }

    if (lane == 0) atomicAdd(&g_counts[winner], 1);

    // gather: 128 floats = 32 lanes x float4
    float4 vv = *reinterpret_cast<const float4*>(cv + (size_t)winner * CVD + lane * 4);
    *reinterpret_cast<float4*>(out + (size_t)r * 256 + g * 128 + lane * 4) = vv;
}

// ---------------- kernel 5: perplexity ----------------
__global__ void ppl_kernel(float* __restrict__ out_scalar) {
    __shared__ float wsum[20];
    int tid = threadIdx.x;
    float m = (float)g_counts[tid] * (1.0f / 16384.0f);
    float term = m * logf(m + 1e-7f);
    #pragma unroll
    for (int off = 16; off > 0; off >>= 1)
        term += __shfl_xor_sync(0xffffffffu, term, off);
    if ((tid & 31) == 0) wsum[tid >> 5] = term;
    __syncthreads();
    if (tid == 0) {
        float s0 = 0.0f, s1 = 0.0f;
        #pragma unroll
        for (int w = 0; w < 10; w++) s0 += wsum[w];
        #pragma unroll
        for (int w = 10; w < 20; w++) s1 += wsum[w];
        *out_scalar = expf(-s0) + expf(-s1);
    }
}

// ---------------- launch ----------------
extern "C" void kernel_launch(void* const* d_in, const int* in_sizes, int n_in,
                              void* d_out, int out_size) {
    const float* hidden = (const float*)d_in[0];
    const float* W      = (const float*)d_in[1];
    const float* bias   = (const float*)d_in[2];
    const float* cv     = (const float*)d_in[3];
    float* out = (float*)d_out;

    cudaFuncSetAttribute(gemm_kernel, cudaFuncAttributeMaxDynamicSharedMemorySize, SM_TOTAL);

    const int convBlocks = (M_DIM * (K_DIM / 4)) / 256;    // 77824
    const int halfBlocks = convBlocks / 2;                 // rows 0..8191 / 8192..16383
    const dim3 gemmGrid(NTILES, (M_DIM / BM) / 2);         // 10 x 64 per half

    if (g_ovl.ok) {
        // fork/join overlap: conv1 runs concurrently with gemm half 0
        conv_a_kernel<<<halfBlocks, 256>>>(hidden, 0);
        trans_w_kernel<<<dim3(N_DIM / 32, K_DIM / 32), 256>>>(W);
        cudaEventRecord(g_ovl.eFork, 0);
        cudaStreamWaitEvent(g_ovl.s1, g_ovl.eFork, 0);
        conv_a_kernel<<<halfBlocks, 256, 0, g_ovl.s1>>>(hidden, halfBlocks * 256);
        cudaEventRecord(g_ovl.eJoin, g_ovl.s1);
        gemm_kernel<<<gemmGrid, 128, SM_TOTAL>>>(bias, 0);
        cudaStreamWaitEvent(0, g_ovl.eJoin, 0);
        gemm_kernel<<<gemmGrid, 128, SM_TOTAL>>>(bias, M_DIM / 2);
        finalize_kernel<<<(M_DIM * NGROUPS) / 8, 256>>>(hidden, bias, cv, out);
        ppl_kernel<<<1, N_DIM>>>(out + (out_size - 1));
    } else {
        // fallback: single-stream sequential (identical math)
        conv_a_kernel<<<halfBlocks, 256>>>(hidden, 0);
        conv_a_kernel<<<halfBlocks, 256>>>(hidden, halfBlocks * 256);
        trans_w_kernel<<<dim3(N_DIM / 32, K_DIM / 32), 256>>>(W);
        gemm_kernel<<<gemmGrid, 128, SM_TOTAL>>>(bias, 0);
        gemm_kernel<<<gemmGrid, 128, SM_TOTAL>>>(bias, M_DIM / 2);
        finalize_kernel<<<(M_DIM * NGROUPS) / 8, 256>>>(hidden, bias, cv, out);
        ppl_kernel<<<1, N_DIM>>>(out + (out_size - 1));
    }
}

// round 13
// speedup vs baseline: 1.0821x; 1.0821x over previous
#include <cuda_runtime.h>
#include <cuda_bf16.h>
#include <cstdint>
#include <math.h>

// Problem constants
#define M_DIM 16384          // B*S
#define K_DIM 4864           // IN_DIM
#define N_DIM 640            // G*V
#define NVARS 320
#define NGROUPS 2
#define CVD   128
#define MARGIN 0.02f

// GEMM tiling: CTA 128x64, 4 warps (2Mx2N), warp tile 64x32, 3 CTAs/SM
#define BM 128
#define BN 64
#define BK 64
#define STAGES 3
#define NKT (K_DIM / BK)                 // 76
#define NTILES (N_DIM / BN)              // 10
#define NSLOT 4

#define SM_A_STAGE (BM * BK * 2)         // 16 KB
#define SM_B_STAGE (BN * BK * 2)         // 8 KB
#define SM_STAGE   (SM_A_STAGE + SM_B_STAGE)  // 24 KB
#define SM_TOTAL   (STAGES * SM_STAGE)   // 72 KB -> 3 CTAs/SM

// ---------------- scratch ----------------
__device__ __nv_bfloat16 g_Abf[(size_t)M_DIM * K_DIM];   // ~159 MB
__device__ __nv_bfloat16 g_Btbf[(size_t)N_DIM * K_DIM];  // ~6.2 MB  W^T bf16 [n][k]
__device__ float         g_Wt[(size_t)N_DIM * K_DIM];    // ~12.5 MB W^T fp32 [n][k]
__device__ float g_candv[(size_t)M_DIM * NTILES * NSLOT]; // 2.6 MB candidate values
__device__ int   g_candc[(size_t)M_DIM * NTILES * NSLOT]; // 2.6 MB candidate cols (global)
__device__ int   g_counts[N_DIM];

// ---------------- stream/event plumbing (created pre-main; no device allocs) ----------------
struct OverlapCtx {
    cudaStream_t s1 = nullptr;
    cudaEvent_t  eFork = nullptr, eJoin = nullptr;
    bool ok = false;
    OverlapCtx() {
        if (cudaStreamCreateWithFlags(&s1, cudaStreamNonBlocking) == cudaSuccess &&
            cudaEventCreateWithFlags(&eFork, cudaEventDisableTiming) == cudaSuccess &&
            cudaEventCreateWithFlags(&eJoin, cudaEventDisableTiming) == cudaSuccess)
            ok = true;
    }
};
static OverlapCtx g_ovl;

// ---------------- helpers ----------------
__device__ __forceinline__ uint32_t smem_u32(const void* p) {
    uint32_t a;
    asm("{ .reg .u64 t; cvta.to.shared.u64 t, %1; cvt.u32.u64 %0, t; }" : "=r"(a) : "l"(p));
    return a;
}
__device__ __forceinline__ void ldsm_x4(uint32_t* r, uint32_t addr) {
    asm volatile("ldmatrix.sync.aligned.m8n8.x4.shared.b16 {%0,%1,%2,%3}, [%4];"
        : "=r"(r[0]), "=r"(r[1]), "=r"(r[2]), "=r"(r[3]) : "r"(addr));
}

// ---------------- kernel 1: convert hidden_states fp32 -> bf16 (range) ----------------
__global__ void conv_a_kernel(const float* __restrict__ A, int base) {
    int i = base + blockIdx.x * blockDim.x + threadIdx.x;
    float4 v = reinterpret_cast<const float4*>(A)[i];
    __nv_bfloat162* o = reinterpret_cast<__nv_bfloat162*>(g_Abf) + (size_t)i * 2;
    o[0] = __floats2bfloat162_rn(v.x, v.y);
    o[1] = __floats2bfloat162_rn(v.z, v.w);
}

// ---------------- kernel 2: transpose W + zero counts ----------------
__global__ void trans_w_kernel(const float* __restrict__ W) {
    __shared__ float tile[32][33];
    const int tx = threadIdx.x & 31;
    const int ty = threadIdx.x >> 5;
    if (blockIdx.x == 0 && blockIdx.y == 0) {
        for (int i = threadIdx.x; i < N_DIM; i += 256) g_counts[i] = 0;
    }
    int x = blockIdx.x * 32 + tx;
    int y0 = blockIdx.y * 32;
    #pragma unroll
    for (int j = ty; j < 32; j += 8)
        tile[j][tx] = W[(size_t)(y0 + j) * N_DIM + x];
    __syncthreads();
    #pragma unroll
    for (int j = ty; j < 32; j += 8) {
        int n = blockIdx.x * 32 + j;
        int k = y0 + tx;
        float val = tile[tx][j];
        g_Wt[(size_t)n * K_DIM + k] = val;
        g_Btbf[(size_t)n * K_DIM + k] = __float2bfloat16_rn(val);
    }
}

// ---------------- kernel 3: bf16 HMMA GEMM + threshold candidate epilogue ----------------
// CTA 128x64, BK=64, 3-stage cp.async, ldmatrix fragments, 4 warps (2Mx2N),
// warp tile 64x32, 3 CTAs/SM, one barrier per K-step. m_base selects the M half.
__global__ __launch_bounds__(128, 3) void gemm_kernel(const float* __restrict__ bias, int m_base) {
    extern __shared__ char smem[];
    const uint32_t su = smem_u32(smem);
    const int tid  = threadIdx.x;
    const int lane = tid & 31;
    const int warp = tid >> 5;       // 0..3
    const int wm = warp >> 1;        // 0..1  (M)
    const int wn = warp & 1;         // 0..1  (N)
    const int cta_m = m_base + blockIdx.y * BM;
    const int cta_n = blockIdx.x * BN;

    float acc[4][4][4];              // [mt][nt][frag]
    #pragma unroll
    for (int a = 0; a < 4; a++)
        #pragma unroll
        for (int b = 0; b < 4; b++)
            #pragma unroll
            for (int c = 0; c < 4; c++) acc[a][b][c] = 0.0f;

    // ---- fragment smem offsets (128B rows; swizzle: chunk ^= row&7) ----
    const int sw = lane & 7;
    uint32_t aOff[4];
    #pragma unroll
    for (int mt = 0; mt < 4; mt++)
        aOff[mt] = (uint32_t)((wm * 64 + mt * 16 + (lane & 15)) * 128);
    const int aChunkHi = lane >> 4;
    uint32_t bOff[2];
    #pragma unroll
    for (int p = 0; p < 2; p++)
        bOff[p] = (uint32_t)((wn * 32 + p * 16 + ((lane >> 4) << 3) + (lane & 7)) * 128);
    const int bChunkHi = (lane >> 3) & 1;

    // ---- stage loader: 16B cp.async, swizzled, 128 threads ----
    const __nv_bfloat16* Ag = g_Abf + (size_t)cta_m * K_DIM;
    const __nv_bfloat16* Bg = g_Btbf + (size_t)cta_n * K_DIM;
    auto load_stage = [&](int kt) {
        const int st = kt % STAGES;
        const int k0 = kt * BK;
        const uint32_t aB = su + st * SM_STAGE;
        const uint32_t bB = aB + SM_A_STAGE;
        #pragma unroll
        for (int i = 0; i < 8; i++) {          // A: 1024 chunks / 128 thr
            int ch = tid + 128 * i;
            int row = ch >> 3, c = ch & 7;
            uint32_t dst = aB + row * 128 + ((c ^ (row & 7)) << 4);
            const void* src = Ag + (size_t)row * K_DIM + k0 + c * 8;
            asm volatile("cp.async.cg.shared.global [%0], [%1], 16;" :: "r"(dst), "l"(src));
        }
        #pragma unroll
        for (int i = 0; i < 4; i++) {          // B: 512 chunks / 128 thr
            int ch = tid + 128 * i;
            int row = ch >> 3, c = ch & 7;
            uint32_t dst = bB + row * 128 + ((c ^ (row & 7)) << 4);
            const void* src = Bg + (size_t)row * K_DIM + k0 + c * 8;
            asm volatile("cp.async.cg.shared.global [%0], [%1], 16;" :: "r"(dst), "l"(src));
        }
    };

    load_stage(0); asm volatile("cp.async.commit_group;");
    load_stage(1); asm volatile("cp.async.commit_group;");

    for (int kt = 0; kt < NKT; kt++) {
        if (kt + 1 < NKT) asm volatile("cp.async.wait_group 1;");
        else              asm volatile("cp.async.wait_group 0;");
        __syncthreads();   // orders stage-kt visibility AND protects stage (kt+2)%3 reuse

        if (kt + 2 < NKT) { load_stage(kt + 2); asm volatile("cp.async.commit_group;"); }

        const uint32_t stBase = su + (kt % STAGES) * SM_STAGE;
        const uint32_t bBase  = stBase + SM_A_STAGE;

        #pragma unroll
        for (int kk = 0; kk < 4; kk++) {
            uint32_t afr[4][4];
            #pragma unroll
            for (int mt = 0; mt < 4; mt++) {
                uint32_t addr = stBase + aOff[mt] + (((kk * 2 + aChunkHi) ^ sw) << 4);
                ldsm_x4(afr[mt], addr);
            }
            uint32_t bfr[2][4];
            #pragma unroll
            for (int p = 0; p < 2; p++) {
                uint32_t addr = bBase + bOff[p] + (((kk * 2 + bChunkHi) ^ sw) << 4);
                ldsm_x4(bfr[p], addr);
            }
            #pragma unroll
            for (int mt = 0; mt < 4; mt++) {
                #pragma unroll
                for (int p = 0; p < 2; p++) {
                    asm volatile(
                        "mma.sync.aligned.m16n8k16.row.col.f32.bf16.bf16.f32 "
                        "{%0,%1,%2,%3}, {%4,%5,%6,%7}, {%8,%9}, {%0,%1,%2,%3};\n"
                        : "+f"(acc[mt][2*p][0]), "+f"(acc[mt][2*p][1]),
                          "+f"(acc[mt][2*p][2]), "+f"(acc[mt][2*p][3])
                        : "r"(afr[mt][0]), "r"(afr[mt][1]), "r"(afr[mt][2]), "r"(afr[mt][3]),
                          "r"(bfr[p][0]), "r"(bfr[p][1]));
                    asm volatile(
                        "mma.sync.aligned.m16n8k16.row.col.f32.bf16.bf16.f32 "
                        "{%0,%1,%2,%3}, {%4,%5,%6,%7}, {%8,%9}, {%0,%1,%2,%3};\n"
                        : "+f"(acc[mt][2*p+1][0]), "+f"(acc[mt][2*p+1][1]),
                          "+f"(acc[mt][2*p+1][2]), "+f"(acc[mt][2*p+1][3])
                        : "r"(afr[mt][0]), "r"(afr[mt][1]), "r"(afr[mt][2]), "r"(afr[mt][3]),
                          "r"(bfr[p][2]), "r"(bfr[p][3]));
                }
            }
        }
    }

    // ---- epilogue: bias + exact threshold candidate extraction ----
    __syncthreads();                      // all LDSM done -> reuse stage smem
    float* sh_max = reinterpret_cast<float*>(smem);              // [128][8]
    float* sh_thr = reinterpret_cast<float*>(smem + 4096);       // [128]
    int*   sh_cnt = reinterpret_cast<int*>(smem + 4608);         // [128]
    float* sh_cv  = reinterpret_cast<float*>(smem + 5120);       // [128][4]
    int*   sh_cc  = reinterpret_cast<int*>(smem + 7168);         // [128][4]

    const int g = lane >> 2;
    const int t = lane & 3;
    // add bias in place
    #pragma unroll
    for (int nt = 0; nt < 4; nt++) {
        float2 bv = *reinterpret_cast<const float2*>(bias + cta_n + wn * 32 + nt * 8 + 2 * t);
        #pragma unroll
        for (int mt = 0; mt < 4; mt++) {
            acc[mt][nt][0] += bv.x; acc[mt][nt][1] += bv.y;
            acc[mt][nt][2] += bv.x; acc[mt][nt][3] += bv.y;
        }
    }
    const int slot = wn * 4 + t;
    // phase A: per-thread row-half max
    #pragma unroll
    for (int mt = 0; mt < 4; mt++) {
        #pragma unroll
        for (int half = 0; half < 2; half++) {
            int rowL = wm * 64 + mt * 16 + g + half * 8;
            float m = -1e30f;
            #pragma unroll
            for (int nt = 0; nt < 4; nt++) {
                m = fmaxf(m, acc[mt][nt][half * 2 + 0]);
                m = fmaxf(m, acc[mt][nt][half * 2 + 1]);
            }
            sh_max[rowL * 8 + slot] = m;
        }
    }
    __syncthreads();
    // phase B: row threshold + init
    if (tid < 128) {
        float m = -1e30f;
        #pragma unroll
        for (int s = 0; s < 8; s++) m = fmaxf(m, sh_max[tid * 8 + s]);
        sh_thr[tid] = m - MARGIN;
        sh_cnt[tid] = 0;
        #pragma unroll
        for (int j = 0; j < NSLOT; j++) { sh_cv[tid * NSLOT + j] = -1e30f; sh_cc[tid * NSLOT + j] = 0; }
    }
    __syncthreads();
    // phase C: scan & push candidates
    #pragma unroll
    for (int mt = 0; mt < 4; mt++) {
        #pragma unroll
        for (int half = 0; half < 2; half++) {
            int rowL = wm * 64 + mt * 16 + g + half * 8;
            float thr = sh_thr[rowL];
            #pragma unroll
            for (int nt = 0; nt < 4; nt++) {
                #pragma unroll
                for (int e = 0; e < 2; e++) {
                    float v = acc[mt][nt][half * 2 + e];
                    if (v >= thr) {
                        int s = atomicAdd(&sh_cnt[rowL], 1);
                        if (s < NSLOT) {
                            sh_cv[rowL * NSLOT + s] = v;
                            sh_cc[rowL * NSLOT + s] = cta_n + wn * 32 + nt * 8 + 2 * t + e;
                        }
                    }
                }
            }
        }
    }
    __syncthreads();
    // phase D: write 4-slot record
    if (tid < 128) {
        size_t gb = ((size_t)(cta_m + tid) * NTILES + blockIdx.x) * NSLOT;
        *reinterpret_cast<float4*>(&g_candv[gb]) = *reinterpret_cast<float4*>(&sh_cv[tid * NSLOT]);
        *reinterpret_cast<int4*>(&g_candc[gb])   = *reinterpret_cast<int4*>(&sh_cc[tid * NSLOT]);
    }
}

// ---------------- kernel 4: finalize = group merge, margin rescue, histogram, gather ----------------
// one warp per (row, group); 8 warps per block
__global__ __launch_bounds__(256) void finalize_kernel(const float* __restrict__ hidden,
                                                       const float* __restrict__ bias,
                                                       const float* __restrict__ cv,
                                                       float* __restrict__ out) {
    const int lane = threadIdx.x & 31;
    const int gw = blockIdx.x * 8 + (threadIdx.x >> 5);  // 0..32767
    const int r = gw >> 1;
    const int g = gw & 1;

    // lanes 0..19 hold the 5 tiles x 4 slots for this group
    float v = -1e30f;
    int   c = 0x7fffffff;
    if (lane < 5 * NSLOT) {
        size_t base = ((size_t)r * NTILES + g * 5 + (lane >> 2)) * NSLOT + (lane & 3);
        v = g_candv[base];
        c = g_candc[base];
    }
    float mx = v;
    #pragma unroll
    for (int off = 16; off > 0; off >>= 1)
        mx = fmaxf(mx, __shfl_xor_sync(0xffffffffu, mx, off));

    unsigned mask = __ballot_sync(0xffffffffu, v >= mx - MARGIN);
    int winner;
    if (__popc(mask) == 1) {
        winner = __shfl_sync(0xffffffffu, c, __ffs(mask) - 1);
    } else {
        // exact fp32 rescore of all candidates; lowest col wins ties
        const float* hrow = hidden + (size_t)r * K_DIM;
        float bb = -INFINITY;
        int bi = 0x7fffffff;
        unsigned m = mask;
        while (m) {
            int src = __ffs(m) - 1;
            m &= m - 1;
            int col = __shfl_sync(0xffffffffu, c, src);   // global col 0..639
            const float* wrow = g_Wt + (size_t)col * K_DIM;
            float s = 0.0f;
            for (int k = lane; k < K_DIM; k += 32)
                s = fmaf(hrow[k], wrow[k], s);
            #pragma unroll
            for (int off = 16; off > 0; off >>= 1)
                s += __shfl_xor_sync(0xffffffffu, s, off);
            s += bias[col];
            if (s > bb || (s == bb && col < bi)) { bb = s; bi = col; }
        }
        winner = bi;
    }

    if (lane == 0) atomicAdd(&g_counts[winner], 1);

    // gather: 128 floats = 32 lanes x float4
    float4 vv = *reinterpret_cast<const float4*>(cv + (size_t)winner * CVD + lane * 4);
    *reinterpret_cast<float4*>(out + (size_t)r * 256 + g * 128 + lane * 4) = vv;
}

// ---------------- kernel 5: perplexity ----------------
__global__ void ppl_kernel(float* __restrict__ out_scalar) {
    __shared__ float wsum[20];
    int tid = threadIdx.x;
    float m = (float)g_counts[tid] * (1.0f / 16384.0f);
    float term = m * logf(m + 1e-7f);
    #pragma unroll
    for (int off = 16; off > 0; off >>= 1)
        term += __shfl_xor_sync(0xffffffffu, term, off);
    if ((tid & 31) == 0) wsum[tid >> 5] = term;
    __syncthreads();
    if (tid == 0) {
        float s0 = 0.0f, s1 = 0.0f;
        #pragma unroll
        for (int w = 0; w < 10; w++) s0 += wsum[w];
        #pragma unroll
        for (int w = 10; w < 20; w++) s1 += wsum[w];
        *out_scalar = expf(-s0) + expf(-s1);
    }
}

// ---------------- launch ----------------
extern "C" void kernel_launch(void* const* d_in, const int* in_sizes, int n_in,
                              void* d_out, int out_size) {
    const float* hidden = (const float*)d_in[0];
    const float* W      = (const float*)d_in[1];
    const float* bias   = (const float*)d_in[2];
    const float* cv     = (const float*)d_in[3];
    float* out = (float*)d_out;

    cudaFuncSetAttribute(gemm_kernel, cudaFuncAttributeMaxDynamicSharedMemorySize, SM_TOTAL);

    const int convBlocks = (M_DIM * (K_DIM / 4)) / 256;    // 77824
    const int halfBlocks = convBlocks / 2;                 // rows 0..8191 / 8192..16383
    const dim3 gemmGrid(NTILES, (M_DIM / BM) / 2);         // 10 x 64 per half

    if (g_ovl.ok) {
        // overlap-v2: both GEMM halves run CONCURRENTLY (no wave boundary);
        // conv1 hides under gemm_half0's ramp.
        conv_a_kernel<<<halfBlocks, 256>>>(hidden, 0);
        trans_w_kernel<<<dim3(N_DIM / 32, K_DIM / 32), 256>>>(W);
        cudaEventRecord(g_ovl.eFork, 0);
        cudaStreamWaitEvent(g_ovl.s1, g_ovl.eFork, 0);
        conv_a_kernel<<<halfBlocks, 256, 0, g_ovl.s1>>>(hidden, halfBlocks * 256);
        gemm_kernel<<<gemmGrid, 128, SM_TOTAL, g_ovl.s1>>>(bias, M_DIM / 2);
        cudaEventRecord(g_ovl.eJoin, g_ovl.s1);
        gemm_kernel<<<gemmGrid, 128, SM_TOTAL>>>(bias, 0);
        cudaStreamWaitEvent(0, g_ovl.eJoin, 0);
        finalize_kernel<<<(M_DIM * NGROUPS) / 8, 256>>>(hidden, bias, cv, out);
        ppl_kernel<<<1, N_DIM>>>(out + (out_size - 1));
    } else {
        // fallback: single-stream sequential (identical math)
        conv_a_kernel<<<halfBlocks, 256>>>(hidden, 0);
        conv_a_kernel<<<halfBlocks, 256>>>(hidden, halfBlocks * 256);
        trans_w_kernel<<<dim3(N_DIM / 32, K_DIM / 32), 256>>>(W);
        gemm_kernel<<<gemmGrid, 128, SM_TOTAL>>>(bias, 0);
        gemm_kernel<<<gemmGrid, 128, SM_TOTAL>>>(bias, M_DIM / 2);
        finalize_kernel<<<(M_DIM * NGROUPS) / 8, 256>>>(hidden, bias, cv, out);
        ppl_kernel<<<1, N_DIM>>>(out + (out_size - 1));
    }
}

// round 14
// speedup vs baseline: 1.0925x; 1.0096x over previous
#include <cuda_runtime.h>
#include <cuda_bf16.h>
#include <cstdint>
#include <math.h>

// Problem constants
#define M_DIM 16384          // B*S
#define K_DIM 4864           // IN_DIM
#define N_DIM 640            // G*V
#define NVARS 320
#define NGROUPS 2
#define CVD   128
#define MARGIN 0.02f

// GEMM tiling: CTA 128x64, 4 warps (2Mx2N), warp tile 64x32, 3 CTAs/SM
#define BM 128
#define BN 64
#define BK 64
#define STAGES 3
#define NKT (K_DIM / BK)                 // 76
#define NTILES (N_DIM / BN)              // 10
#define NSLOT 4

#define SM_A_STAGE (BM * BK * 2)         // 16 KB
#define SM_B_STAGE (BN * BK * 2)         // 8 KB
#define SM_STAGE   (SM_A_STAGE + SM_B_STAGE)  // 24 KB
#define SM_TOTAL   (STAGES * SM_STAGE)   // 72 KB -> 3 CTAs/SM

// ---------------- scratch ----------------
__device__ __nv_bfloat16 g_Abf[(size_t)M_DIM * K_DIM];   // ~159 MB
__device__ __nv_bfloat16 g_Btbf[(size_t)N_DIM * K_DIM];  // ~6.2 MB  W^T bf16 [n][k]
__device__ float         g_Wt[(size_t)N_DIM * K_DIM];    // ~12.5 MB W^T fp32 [n][k]
__device__ float g_candv[(size_t)M_DIM * NTILES * NSLOT]; // 2.6 MB candidate values
__device__ int   g_candc[(size_t)M_DIM * NTILES * NSLOT]; // 2.6 MB candidate cols (global)
__device__ int   g_counts[N_DIM];

// ---------------- stream/event plumbing (created pre-main; no device allocs) ----------------
struct OverlapCtx {
    cudaStream_t s1 = nullptr;
    cudaEvent_t  eFork = nullptr, eJoin = nullptr;
    bool ok = false;
    OverlapCtx() {
        if (cudaStreamCreateWithFlags(&s1, cudaStreamNonBlocking) == cudaSuccess &&
            cudaEventCreateWithFlags(&eFork, cudaEventDisableTiming) == cudaSuccess &&
            cudaEventCreateWithFlags(&eJoin, cudaEventDisableTiming) == cudaSuccess)
            ok = true;
    }
};
static OverlapCtx g_ovl;

// ---------------- helpers ----------------
__device__ __forceinline__ uint32_t smem_u32(const void* p) {
    uint32_t a;
    asm("{ .reg .u64 t; cvta.to.shared.u64 t, %1; cvt.u32.u64 %0, t; }" : "=r"(a) : "l"(p));
    return a;
}
__device__ __forceinline__ void ldsm_x4(uint32_t* r, uint32_t addr) {
    asm volatile("ldmatrix.sync.aligned.m8n8.x4.shared.b16 {%0,%1,%2,%3}, [%4];"
        : "=r"(r[0]), "=r"(r[1]), "=r"(r[2]), "=r"(r[3]) : "r"(addr));
}

// ---------------- kernel 1: convert hidden_states fp32 -> bf16 (range) ----------------
__global__ void conv_a_kernel(const float* __restrict__ A, int base) {
    int i = base + blockIdx.x * blockDim.x + threadIdx.x;
    float4 v = reinterpret_cast<const float4*>(A)[i];
    __nv_bfloat162* o = reinterpret_cast<__nv_bfloat162*>(g_Abf) + (size_t)i * 2;
    o[0] = __floats2bfloat162_rn(v.x, v.y);
    o[1] = __floats2bfloat162_rn(v.z, v.w);
}

// ---------------- kernel 2: transpose W + zero counts ----------------
__global__ void trans_w_kernel(const float* __restrict__ W) {
    __shared__ float tile[32][33];
    const int tx = threadIdx.x & 31;
    const int ty = threadIdx.x >> 5;
    if (blockIdx.x == 0 && blockIdx.y == 0) {
        for (int i = threadIdx.x; i < N_DIM; i += 256) g_counts[i] = 0;
    }
    int x = blockIdx.x * 32 + tx;
    int y0 = blockIdx.y * 32;
    #pragma unroll
    for (int j = ty; j < 32; j += 8)
        tile[j][tx] = W[(size_t)(y0 + j) * N_DIM + x];
    __syncthreads();
    #pragma unroll
    for (int j = ty; j < 32; j += 8) {
        int n = blockIdx.x * 32 + j;
        int k = y0 + tx;
        float val = tile[tx][j];
        g_Wt[(size_t)n * K_DIM + k] = val;
        g_Btbf[(size_t)n * K_DIM + k] = __float2bfloat16_rn(val);
    }
}

// ---------------- kernel 3: bf16 HMMA GEMM + threshold candidate epilogue ----------------
// CTA 128x64, BK=64, 3-stage cp.async, ldmatrix fragments, 4 warps (2Mx2N),
// warp tile 64x32, 3 CTAs/SM, one barrier per K-step. m_base selects the M half.
__global__ __launch_bounds__(128, 3) void gemm_kernel(const float* __restrict__ bias, int m_base) {
    extern __shared__ char smem[];
    const uint32_t su = smem_u32(smem);
    const int tid  = threadIdx.x;
    const int lane = tid & 31;
    const int warp = tid >> 5;       // 0..3
    const int wm = warp >> 1;        // 0..1  (M)
    const int wn = warp & 1;         // 0..1  (N)
    const int cta_m = m_base + blockIdx.y * BM;
    const int cta_n = blockIdx.x * BN;

    float acc[4][4][4];              // [mt][nt][frag]
    #pragma unroll
    for (int a = 0; a < 4; a++)
        #pragma unroll
        for (int b = 0; b < 4; b++)
            #pragma unroll
            for (int c = 0; c < 4; c++) acc[a][b][c] = 0.0f;

    // ---- fragment smem offsets (128B rows; swizzle: chunk ^= row&7) ----
    const int sw = lane & 7;
    uint32_t aOff[4];
    #pragma unroll
    for (int mt = 0; mt < 4; mt++)
        aOff[mt] = (uint32_t)((wm * 64 + mt * 16 + (lane & 15)) * 128);
    const int aChunkHi = lane >> 4;
    uint32_t bOff[2];
    #pragma unroll
    for (int p = 0; p < 2; p++)
        bOff[p] = (uint32_t)((wn * 32 + p * 16 + ((lane >> 4) << 3) + (lane & 7)) * 128);
    const int bChunkHi = (lane >> 3) & 1;

    // ---- stage loader: 16B cp.async, swizzled, 128 threads ----
    const __nv_bfloat16* Ag = g_Abf + (size_t)cta_m * K_DIM;
    const __nv_bfloat16* Bg = g_Btbf + (size_t)cta_n * K_DIM;
    auto load_stage = [&](int kt) {
        const int st = kt % STAGES;
        const int k0 = kt * BK;
        const uint32_t aB = su + st * SM_STAGE;
        const uint32_t bB = aB + SM_A_STAGE;
        #pragma unroll
        for (int i = 0; i < 8; i++) {          // A: 1024 chunks / 128 thr
            int ch = tid + 128 * i;
            int row = ch >> 3, c = ch & 7;
            uint32_t dst = aB + row * 128 + ((c ^ (row & 7)) << 4);
            const void* src = Ag + (size_t)row * K_DIM + k0 + c * 8;
            asm volatile("cp.async.cg.shared.global [%0], [%1], 16;" :: "r"(dst), "l"(src));
        }
        #pragma unroll
        for (int i = 0; i < 4; i++) {          // B: 512 chunks / 128 thr
            int ch = tid + 128 * i;
            int row = ch >> 3, c = ch & 7;
            uint32_t dst = bB + row * 128 + ((c ^ (row & 7)) << 4);
            const void* src = Bg + (size_t)row * K_DIM + k0 + c * 8;
            asm volatile("cp.async.cg.shared.global [%0], [%1], 16;" :: "r"(dst), "l"(src));
        }
    };

    load_stage(0); asm volatile("cp.async.commit_group;");
    load_stage(1); asm volatile("cp.async.commit_group;");

    for (int kt = 0; kt < NKT; kt++) {
        if (kt + 1 < NKT) asm volatile("cp.async.wait_group 1;");
        else              asm volatile("cp.async.wait_group 0;");
        __syncthreads();   // orders stage-kt visibility AND protects stage (kt+2)%3 reuse

        if (kt + 2 < NKT) { load_stage(kt + 2); asm volatile("cp.async.commit_group;"); }

        const uint32_t stBase = su + (kt % STAGES) * SM_STAGE;
        const uint32_t bBase  = stBase + SM_A_STAGE;

        #pragma unroll
        for (int kk = 0; kk < 4; kk++) {
            uint32_t afr[4][4];
            #pragma unroll
            for (int mt = 0; mt < 4; mt++) {
                uint32_t addr = stBase + aOff[mt] + (((kk * 2 + aChunkHi) ^ sw) << 4);
                ldsm_x4(afr[mt], addr);
            }
            uint32_t bfr[2][4];
            #pragma unroll
            for (int p = 0; p < 2; p++) {
                uint32_t addr = bBase + bOff[p] + (((kk * 2 + bChunkHi) ^ sw) << 4);
                ldsm_x4(bfr[p], addr);
            }
            #pragma unroll
            for (int mt = 0; mt < 4; mt++) {
                #pragma unroll
                for (int p = 0; p < 2; p++) {
                    asm volatile(
                        "mma.sync.aligned.m16n8k16.row.col.f32.bf16.bf16.f32 "
                        "{%0,%1,%2,%3}, {%4,%5,%6,%7}, {%8,%9}, {%0,%1,%2,%3};\n"
                        : "+f"(acc[mt][2*p][0]), "+f"(acc[mt][2*p][1]),
                          "+f"(acc[mt][2*p][2]), "+f"(acc[mt][2*p][3])
                        : "r"(afr[mt][0]), "r"(afr[mt][1]), "r"(afr[mt][2]), "r"(afr[mt][3]),
                          "r"(bfr[p][0]), "r"(bfr[p][1]));
                    asm volatile(
                        "mma.sync.aligned.m16n8k16.row.col.f32.bf16.bf16.f32 "
                        "{%0,%1,%2,%3}, {%4,%5,%6,%7}, {%8,%9}, {%0,%1,%2,%3};\n"
                        : "+f"(acc[mt][2*p+1][0]), "+f"(acc[mt][2*p+1][1]),
                          "+f"(acc[mt][2*p+1][2]), "+f"(acc[mt][2*p+1][3])
                        : "r"(afr[mt][0]), "r"(afr[mt][1]), "r"(afr[mt][2]), "r"(afr[mt][3]),
                          "r"(bfr[p][2]), "r"(bfr[p][3]));
                }
            }
        }
    }

    // ---- epilogue: bias + exact threshold candidate extraction ----
    __syncthreads();                      // all LDSM done -> reuse stage smem
    float* sh_max = reinterpret_cast<float*>(smem);              // [128][8]
    float* sh_thr = reinterpret_cast<float*>(smem + 4096);       // [128]
    int*   sh_cnt = reinterpret_cast<int*>(smem + 4608);         // [128]
    float* sh_cv  = reinterpret_cast<float*>(smem + 5120);       // [128][4]
    int*   sh_cc  = reinterpret_cast<int*>(smem + 7168);         // [128][4]

    const int g = lane >> 2;
    const int t = lane & 3;
    // add bias in place
    #pragma unroll
    for (int nt = 0; nt < 4; nt++) {
        float2 bv = *reinterpret_cast<const float2*>(bias + cta_n + wn * 32 + nt * 8 + 2 * t);
        #pragma unroll
        for (int mt = 0; mt < 4; mt++) {
            acc[mt][nt][0] += bv.x; acc[mt][nt][1] += bv.y;
            acc[mt][nt][2] += bv.x; acc[mt][nt][3] += bv.y;
        }
    }
    const int slot = wn * 4 + t;
    // phase A: per-thread row-half max
    #pragma unroll
    for (int mt = 0; mt < 4; mt++) {
        #pragma unroll
        for (int half = 0; half < 2; half++) {
            int rowL = wm * 64 + mt * 16 + g + half * 8;
            float m = -1e30f;
            #pragma unroll
            for (int nt = 0; nt < 4; nt++) {
                m = fmaxf(m, acc[mt][nt][half * 2 + 0]);
                m = fmaxf(m, acc[mt][nt][half * 2 + 1]);
            }
            sh_max[rowL * 8 + slot] = m;
        }
    }
    __syncthreads();
    // phase B: row threshold + init
    if (tid < 128) {
        float m = -1e30f;
        #pragma unroll
        for (int s = 0; s < 8; s++) m = fmaxf(m, sh_max[tid * 8 + s]);
        sh_thr[tid] = m - MARGIN;
        sh_cnt[tid] = 0;
        #pragma unroll
        for (int j = 0; j < NSLOT; j++) { sh_cv[tid * NSLOT + j] = -1e30f; sh_cc[tid * NSLOT + j] = 0; }
    }
    __syncthreads();
    // phase C: scan & push candidates
    #pragma unroll
    for (int mt = 0; mt < 4; mt++) {
        #pragma unroll
        for (int half = 0; half < 2; half++) {
            int rowL = wm * 64 + mt * 16 + g + half * 8;
            float thr = sh_thr[rowL];
            #pragma unroll
            for (int nt = 0; nt < 4; nt++) {
                #pragma unroll
                for (int e = 0; e < 2; e++) {
                    float v = acc[mt][nt][half * 2 + e];
                    if (v >= thr) {
                        int s = atomicAdd(&sh_cnt[rowL], 1);
                        if (s < NSLOT) {
                            sh_cv[rowL * NSLOT + s] = v;
                            sh_cc[rowL * NSLOT + s] = cta_n + wn * 32 + nt * 8 + 2 * t + e;
                        }
                    }
                }
            }
        }
    }
    __syncthreads();
    // phase D: write 4-slot record
    if (tid < 128) {
        size_t gb = ((size_t)(cta_m + tid) * NTILES + blockIdx.x) * NSLOT;
        *reinterpret_cast<float4*>(&g_candv[gb]) = *reinterpret_cast<float4*>(&sh_cv[tid * NSLOT]);
        *reinterpret_cast<int4*>(&g_candc[gb])   = *reinterpret_cast<int4*>(&sh_cc[tid * NSLOT]);
    }
}

// ---------------- kernel 4: finalize = group merge, margin rescue, histogram, gather ----------------
// one warp per (row, group); 8 warps per block; r_base selects the row half
__global__ __launch_bounds__(256) void finalize_kernel(const float* __restrict__ hidden,
                                                       const float* __restrict__ bias,
                                                       const float* __restrict__ cv,
                                                       float* __restrict__ out,
                                                       int r_base) {
    const int lane = threadIdx.x & 31;
    const int gw = blockIdx.x * 8 + (threadIdx.x >> 5);
    const int r = r_base + (gw >> 1);
    const int g = gw & 1;

    // lanes 0..19 hold the 5 tiles x 4 slots for this group
    float v = -1e30f;
    int   c = 0x7fffffff;
    if (lane < 5 * NSLOT) {
        size_t base = ((size_t)r * NTILES + g * 5 + (lane >> 2)) * NSLOT + (lane & 3);
        v = g_candv[base];
        c = g_candc[base];
    }
    float mx = v;
    #pragma unroll
    for (int off = 16; off > 0; off >>= 1)
        mx = fmaxf(mx, __shfl_xor_sync(0xffffffffu, mx, off));

    unsigned mask = __ballot_sync(0xffffffffu, v >= mx - MARGIN);
    int winner;
    if (__popc(mask) == 1) {
        winner = __shfl_sync(0xffffffffu, c, __ffs(mask) - 1);
    } else {
        // exact fp32 rescore of all candidates; lowest col wins ties
        const float* hrow = hidden + (size_t)r * K_DIM;
        float bb = -INFINITY;
        int bi = 0x7fffffff;
        unsigned m = mask;
        while (m) {
            int src = __ffs(m) - 1;
            m &= m - 1;
            int col = __shfl_sync(0xffffffffu, c, src);   // global col 0..639
            const float* wrow = g_Wt + (size_t)col * K_DIM;
            float s = 0.0f;
            for (int k = lane; k < K_DIM; k += 32)
                s = fmaf(hrow[k], wrow[k], s);
            #pragma unroll
            for (int off = 16; off > 0; off >>= 1)
                s += __shfl_xor_sync(0xffffffffu, s, off);
            s += bias[col];
            if (s > bb || (s == bb && col < bi)) { bb = s; bi = col; }
        }
        winner = bi;
    }

    if (lane == 0) atomicAdd(&g_counts[winner], 1);

    // gather: 128 floats = 32 lanes x float4
    float4 vv = *reinterpret_cast<const float4*>(cv + (size_t)winner * CVD + lane * 4);
    *reinterpret_cast<float4*>(out + (size_t)r * 256 + g * 128 + lane * 4) = vv;
}

// ---------------- kernel 5: perplexity ----------------
__global__ void ppl_kernel(float* __restrict__ out_scalar) {
    __shared__ float wsum[20];
    int tid = threadIdx.x;
    float m = (float)g_counts[tid] * (1.0f / 16384.0f);
    float term = m * logf(m + 1e-7f);
    #pragma unroll
    for (int off = 16; off > 0; off >>= 1)
        term += __shfl_xor_sync(0xffffffffu, term, off);
    if ((tid & 31) == 0) wsum[tid >> 5] = term;
    __syncthreads();
    if (tid == 0) {
        float s0 = 0.0f, s1 = 0.0f;
        #pragma unroll
        for (int w = 0; w < 10; w++) s0 += wsum[w];
        #pragma unroll
        for (int w = 10; w < 20; w++) s1 += wsum[w];
        *out_scalar = expf(-s0) + expf(-s1);
    }
}

// ---------------- launch ----------------
extern "C" void kernel_launch(void* const* d_in, const int* in_sizes, int n_in,
                              void* d_out, int out_size) {
    const float* hidden = (const float*)d_in[0];
    const float* W      = (const float*)d_in[1];
    const float* bias   = (const float*)d_in[2];
    const float* cv     = (const float*)d_in[3];
    float* out = (float*)d_out;

    cudaFuncSetAttribute(gemm_kernel, cudaFuncAttributeMaxDynamicSharedMemorySize, SM_TOTAL);

    const int convBlocks = (M_DIM * (K_DIM / 4)) / 256;    // 77824
    const int halfBlocks = convBlocks / 2;                 // rows 0..8191 / 8192..16383
    const dim3 gemmGrid(NTILES, (M_DIM / BM) / 2);         // 10 x 64 per half
    const int finHalfGrid = ((M_DIM / 2) * NGROUPS) / 8;   // 2048 blocks per half

    if (g_ovl.ok) {
        // overlap-v3: per-half tail pipelining.
        // s0: transw -> conv0 -> eFork -> gemm_h0 -> finalize_h0 -> wait eJoin -> ppl
        // s1: wait eFork -> conv1 -> gemm_h1 -> finalize_h1 -> eJoin
        trans_w_kernel<<<dim3(N_DIM / 32, K_DIM / 32), 256>>>(W);
        conv_a_kernel<<<halfBlocks, 256>>>(hidden, 0);
        cudaEventRecord(g_ovl.eFork, 0);
        cudaStreamWaitEvent(g_ovl.s1, g_ovl.eFork, 0);
        conv_a_kernel<<<halfBlocks, 256, 0, g_ovl.s1>>>(hidden, halfBlocks * 256);
        gemm_kernel<<<gemmGrid, 128, SM_TOTAL, g_ovl.s1>>>(bias, M_DIM / 2);
        gemm_kernel<<<gemmGrid, 128, SM_TOTAL>>>(bias, 0);
        finalize_kernel<<<finHalfGrid, 256>>>(hidden, bias, cv, out, 0);
        finalize_kernel<<<finHalfGrid, 256, 0, g_ovl.s1>>>(hidden, bias, cv, out, M_DIM / 2);
        cudaEventRecord(g_ovl.eJoin, g_ovl.s1);
        cudaStreamWaitEvent(0, g_ovl.eJoin, 0);
        ppl_kernel<<<1, N_DIM>>>(out + (out_size - 1));
    } else {
        // fallback: single-stream sequential (identical math)
        trans_w_kernel<<<dim3(N_DIM / 32, K_DIM / 32), 256>>>(W);
        conv_a_kernel<<<halfBlocks, 256>>>(hidden, 0);
        conv_a_kernel<<<halfBlocks, 256>>>(hidden, halfBlocks * 256);
        gemm_kernel<<<gemmGrid, 128, SM_TOTAL>>>(bias, 0);
        gemm_kernel<<<gemmGrid, 128, SM_TOTAL>>>(bias, M_DIM / 2);
        finalize_kernel<<<finHalfGrid, 256>>>(hidden, bias, cv, out, 0);
        finalize_kernel<<<finHalfGrid, 256>>>(hidden, bias, cv, out, M_DIM / 2);
        ppl_kernel<<<1, N_DIM>>>(out + (out_size - 1));
    }
}